// round 5
// baseline (speedup 1.0000x reference)
#include <cuda_runtime.h>

// LightweightConv1d: out[b,c,t] = sum_k softmax(w[c%16])[k] * x[b,c,t+k-3]
// x: (16,1024,4096) fp32, w: (16,1,7) fp32, 'same' padding (P=3), K=7.
// HBM-bound streaming kernel: 256MB in + 256MB out.

#define SEQ_T      4096
#define KTAPS      7
#define PAD        3
#define NTHREADS   256
#define HEADS      16

__global__ __launch_bounds__(NTHREADS) void lconv1d_kernel(
    const float* __restrict__ x,
    const float* __restrict__ w,
    float* __restrict__ out)
{
    // smem layout: s[4 + t] = x[row, t]; s[1..3] and s[4+T..4+T+2] are zero halo.
    // +8 tail pad so the last aligned float4 read (floats 4100..4103) is in-bounds.
    __shared__ __align__(16) float s[4 + SEQ_T + 8];

    const int row  = blockIdx.x;           // row = b*1024 + c, 0..16383
    const int tid  = threadIdx.x;
    const int head = row & (HEADS - 1);    // c % 16 (1024 % 16 == 0)

    // --- softmax over the 7 taps (weight tensor is 448B, L1-resident) ---
    float wv[KTAPS];
    float m = -1e30f;
    #pragma unroll
    for (int k = 0; k < KTAPS; k++) {
        wv[k] = __ldg(&w[head * KTAPS + k]);
        m = fmaxf(m, wv[k]);
    }
    float sum = 0.0f;
    #pragma unroll
    for (int k = 0; k < KTAPS; k++) { wv[k] = __expf(wv[k] - m); sum += wv[k]; }
    const float inv = 1.0f / sum;
    #pragma unroll
    for (int k = 0; k < KTAPS; k++) wv[k] *= inv;

    // --- stage row into smem (float4, fully coalesced) ---
    const float4* xr = (const float4*)(x + (size_t)row * SEQ_T);
    float4* s4 = (float4*)(s + 4);
    #pragma unroll
    for (int i = 0; i < SEQ_T / 4 / NTHREADS; i++)
        s4[tid + NTHREADS * i] = xr[tid + NTHREADS * i];

    if (tid < 4)                s[tid] = 0.0f;                  // s[0..3]  (left halo + pad)
    else if (tid < 8)           s[4 + SEQ_T + (tid - 4)] = 0.0f; // s[4100..4103] (right halo + pad)
    __syncthreads();

    // --- compute: 4 outputs per iter per thread, 4 iters = 16 outputs/thread ---
    const float4* sv = (const float4*)s;
    float4* o4 = (float4*)(out + (size_t)row * SEQ_T);

    #pragma unroll
    for (int i = 0; i < 4; i++) {
        const int t0 = 4 * tid + (NTHREADS * 4) * i;   // output base, float4-aligned
        const int bi = 1 + (t0 >> 2);                  // float4 index of x[t0..t0+3] in s

        // v[j] = x[t0 - 4 + j], j = 0..11 (v0, v11 unused)
        const float4 A = sv[bi - 1];
        const float4 B = sv[bi];
        const float4 C = sv[bi + 1];
        const float v1 = A.y, v2 = A.z, v3 = A.w;
        const float v4 = B.x, v5 = B.y, v6 = B.z, v7 = B.w;
        const float v8 = C.x, v9 = C.y, v10 = C.z;

        float4 r;
        r.x = wv[0]*v1 + wv[1]*v2 + wv[2]*v3 + wv[3]*v4 + wv[4]*v5 + wv[5]*v6 + wv[6]*v7;
        r.y = wv[0]*v2 + wv[1]*v3 + wv[2]*v4 + wv[3]*v5 + wv[4]*v6 + wv[5]*v7 + wv[6]*v8;
        r.z = wv[0]*v3 + wv[1]*v4 + wv[2]*v5 + wv[3]*v6 + wv[4]*v7 + wv[5]*v8 + wv[6]*v9;
        r.w = wv[0]*v4 + wv[1]*v5 + wv[2]*v6 + wv[3]*v7 + wv[4]*v8 + wv[5]*v9 + wv[6]*v10;

        o4[t0 >> 2] = r;
    }
}

extern "C" void kernel_launch(void* const* d_in, const int* in_sizes, int n_in,
                              void* d_out, int out_size) {
    const float* x = (const float*)d_in[0];   // (16,1024,4096) fp32
    const float* w = (const float*)d_in[1];   // (16,1,7) fp32
    float* out = (float*)d_out;

    const int rows = in_sizes[0] / SEQ_T;     // 16384
    lconv1d_kernel<<<rows, NTHREADS>>>(x, w, out);
}

// round 6
// speedup vs baseline: 1.0071x; 1.0071x over previous
#include <cuda_runtime.h>

// LightweightConv1d: out[b,c,t] = sum_k softmax(w[c%16])[k] * x[b,c,t+k-3]
// x: (16,1024,4096) fp32, w: (16,1,7) fp32, 'same' padding (P=3), K=7.
// HBM-bound streaming kernel: 256MB in + 256MB out.

#define SEQ_T      4096
#define KTAPS      7
#define PAD        3
#define NTHREADS   256
#define HEADS      16

__global__ __launch_bounds__(NTHREADS) void lconv1d_kernel(
    const float* __restrict__ x,
    const float* __restrict__ w,
    float* __restrict__ out)
{
    // smem layout: s[4 + t] = x[row, t]; s[1..3] and s[4+T..4+T+2] are zero halo.
    // +8 tail pad so the last aligned float4 read (floats 4100..4103) is in-bounds.
    __shared__ __align__(16) float s[4 + SEQ_T + 8];

    const int row  = blockIdx.x;           // row = b*1024 + c, 0..16383
    const int tid  = threadIdx.x;
    const int head = row & (HEADS - 1);    // c % 16 (1024 % 16 == 0)

    // --- softmax over the 7 taps (weight tensor is 448B, L1-resident) ---
    float wv[KTAPS];
    float m = -1e30f;
    #pragma unroll
    for (int k = 0; k < KTAPS; k++) {
        wv[k] = __ldg(&w[head * KTAPS + k]);
        m = fmaxf(m, wv[k]);
    }
    float sum = 0.0f;
    #pragma unroll
    for (int k = 0; k < KTAPS; k++) { wv[k] = __expf(wv[k] - m); sum += wv[k]; }
    const float inv = 1.0f / sum;
    #pragma unroll
    for (int k = 0; k < KTAPS; k++) wv[k] *= inv;

    // --- stage row into smem (float4, fully coalesced) ---
    const float4* xr = (const float4*)(x + (size_t)row * SEQ_T);
    float4* s4 = (float4*)(s + 4);
    #pragma unroll
    for (int i = 0; i < SEQ_T / 4 / NTHREADS; i++)
        s4[tid + NTHREADS * i] = xr[tid + NTHREADS * i];

    if (tid < 4)                s[tid] = 0.0f;                  // s[0..3]  (left halo + pad)
    else if (tid < 8)           s[4 + SEQ_T + (tid - 4)] = 0.0f; // s[4100..4103] (right halo + pad)
    __syncthreads();

    // --- compute: 4 outputs per iter per thread, 4 iters = 16 outputs/thread ---
    const float4* sv = (const float4*)s;
    float4* o4 = (float4*)(out + (size_t)row * SEQ_T);

    #pragma unroll
    for (int i = 0; i < 4; i++) {
        const int t0 = 4 * tid + (NTHREADS * 4) * i;   // output base, float4-aligned
        const int bi = 1 + (t0 >> 2);                  // float4 index of x[t0..t0+3] in s

        // v[j] = x[t0 - 4 + j], j = 0..11 (v0, v11 unused)
        const float4 A = sv[bi - 1];
        const float4 B = sv[bi];
        const float4 C = sv[bi + 1];
        const float v1 = A.y, v2 = A.z, v3 = A.w;
        const float v4 = B.x, v5 = B.y, v6 = B.z, v7 = B.w;
        const float v8 = C.x, v9 = C.y, v10 = C.z;

        float4 r;
        r.x = wv[0]*v1 + wv[1]*v2 + wv[2]*v3 + wv[3]*v4 + wv[4]*v5 + wv[5]*v6 + wv[6]*v7;
        r.y = wv[0]*v2 + wv[1]*v3 + wv[2]*v4 + wv[3]*v5 + wv[4]*v6 + wv[5]*v7 + wv[6]*v8;
        r.z = wv[0]*v3 + wv[1]*v4 + wv[2]*v5 + wv[3]*v6 + wv[4]*v7 + wv[5]*v8 + wv[6]*v9;
        r.w = wv[0]*v4 + wv[1]*v5 + wv[2]*v6 + wv[3]*v7 + wv[4]*v8 + wv[5]*v9 + wv[6]*v10;

        o4[t0 >> 2] = r;
    }
}

extern "C" void kernel_launch(void* const* d_in, const int* in_sizes, int n_in,
                              void* d_out, int out_size) {
    const float* x = (const float*)d_in[0];   // (16,1024,4096) fp32
    const float* w = (const float*)d_in[1];   // (16,1,7) fp32
    float* out = (float*)d_out;

    const int rows = in_sizes[0] / SEQ_T;     // 16384
    lconv1d_kernel<<<rows, NTHREADS>>>(x, w, out);
}